// round 1
// baseline (speedup 1.0000x reference)
#include <cuda_runtime.h>
#include <cuda_bf16.h>
#include <mma.h>

using namespace nvcuda;

#define BATCH 16384
#define EMBED 256
#define NS    4096
#define VOCAB 50000

// ---------------- device scratch (no cudaMalloc allowed) ----------------
__device__ __align__(16) __nv_bfloat16 g_A[BATCH * EMBED];  // bf16 embedding
__device__ __align__(16) __nv_bfloat16 g_B[NS * EMBED];     // bf16 gathered sampled weights
__device__ float g_c[NS];                                   // bias[id] - log(expected_count(id))
__device__ float g_partial[BATCH];                          // per-example loss

__device__ __forceinline__ float neg_log_ec(float fid) {
    // p = (log(id+2)-log(id+1)) / log(VOCAB+1); ec = -expm1(NS*log1p(-p))
    const float inv_logv = 1.0f / logf((float)VOCAB + 1.0f);
    float p  = (logf(fid + 2.0f) - logf(fid + 1.0f)) * inv_logv;
    float ec = -expm1f((float)NS * log1pf(-p));
    return -logf(ec);
}

// ---------------- prep: embedding fp32 -> bf16 ----------------
__global__ void k_prep_A(const float* __restrict__ emb) {
    int i = blockIdx.x * 256 + threadIdx.x;          // each handles 8 floats
    if (i >= BATCH * 32) return;
    int row = i >> 5;
    int d8  = (i & 31) << 3;
    const float4* src = (const float4*)(emb + (size_t)row * EMBED + d8);
    float4 x = src[0], y = src[1];
    __align__(16) __nv_bfloat162 p[4];
    p[0] = __floats2bfloat162_rn(x.x, x.y);
    p[1] = __floats2bfloat162_rn(x.z, x.w);
    p[2] = __floats2bfloat162_rn(y.x, y.y);
    p[3] = __floats2bfloat162_rn(y.z, y.w);
    *(uint4*)(g_A + (size_t)row * EMBED + d8) = *(const uint4*)p;
}

// ---------------- prep: gather sampled weight rows -> bf16 ----------------
__global__ void k_prep_B(const int* __restrict__ sids, const float* __restrict__ W) {
    int i = blockIdx.x * 256 + threadIdx.x;
    if (i >= NS * 32) return;
    int s  = i >> 5;
    int d8 = (i & 31) << 3;
    int id = sids[s];
    const float4* src = (const float4*)(W + (size_t)id * EMBED + d8);
    float4 x = src[0], y = src[1];
    __align__(16) __nv_bfloat162 p[4];
    p[0] = __floats2bfloat162_rn(x.x, x.y);
    p[1] = __floats2bfloat162_rn(x.z, x.w);
    p[2] = __floats2bfloat162_rn(y.x, y.y);
    p[3] = __floats2bfloat162_rn(y.z, y.w);
    *(uint4*)(g_B + (size_t)s * EMBED + d8) = *(const uint4*)p;
}

// ---------------- prep: per-sample offsets ----------------
__global__ void k_prep_c(const int* __restrict__ sids, const float* __restrict__ bias) {
    int s = blockIdx.x * 256 + threadIdx.x;
    if (s >= NS) return;
    int id = sids[s];
    g_c[s] = bias[id] + neg_log_ec((float)id);
}

// ---------------- fused GEMM + softplus row-sum ----------------
// BM=64 rows of batch per block, sweep all NS columns in BN=128 tiles.
#define BM 64
#define BN 128
#define BK 64
#define LDA 72
#define LDB 72
#define LDC 136

__global__ __launch_bounds__(256, 2) void k_gemm() {
    __shared__ __align__(16) unsigned char sm[BM * LDC * 4];   // 34816 B, aliased
    __shared__ float rowAcc[BM];

    __nv_bfloat16* A_s = (__nv_bfloat16*)sm;                    // [BM][LDA]
    __nv_bfloat16* B_s = (__nv_bfloat16*)(sm + BM * LDA * 2);   // [BN][LDB]
    float*         C_s = (float*)sm;                            // [BM][LDC]

    const int m0   = blockIdx.x * BM;
    const int tid  = threadIdx.x;
    const int warp = tid >> 5;
    const int wm   = warp & 1;   // 2 M-groups of 32
    const int wn   = warp >> 1;  // 4 N-groups of 32

    if (tid < BM) rowAcc[tid] = 0.0f;

    for (int nt = 0; nt < NS / BN; nt++) {
        const int n0 = nt * BN;

        wmma::fragment<wmma::accumulator, 16, 16, 16, float> c[2][2];
        #pragma unroll
        for (int i = 0; i < 2; i++)
            #pragma unroll
            for (int j = 0; j < 2; j++) wmma::fill_fragment(c[i][j], 0.0f);

        for (int k0 = 0; k0 < EMBED; k0 += BK) {
            __syncthreads();   // previous readers (mma/epilogue) done
            // load A chunk: 64x64 bf16 = 512 uint4
            #pragma unroll
            for (int i = 0; i < 2; i++) {
                int idx = tid + i * 256;
                int r = idx >> 3;
                int ccol = (idx & 7) << 3;
                *(uint4*)&A_s[r * LDA + ccol] =
                    *(const uint4*)&g_A[(size_t)(m0 + r) * EMBED + k0 + ccol];
            }
            // load B chunk: 128x64 bf16 = 1024 uint4
            #pragma unroll
            for (int i = 0; i < 4; i++) {
                int idx = tid + i * 256;
                int r = idx >> 3;
                int ccol = (idx & 7) << 3;
                *(uint4*)&B_s[r * LDB + ccol] =
                    *(const uint4*)&g_B[(size_t)(n0 + r) * EMBED + k0 + ccol];
            }
            __syncthreads();

            #pragma unroll
            for (int kk = 0; kk < BK; kk += 16) {
                wmma::fragment<wmma::matrix_a, 16, 16, 16, __nv_bfloat16, wmma::row_major> a0, a1;
                wmma::fragment<wmma::matrix_b, 16, 16, 16, __nv_bfloat16, wmma::col_major> b0, b1;
                wmma::load_matrix_sync(a0, &A_s[(wm * 32 + 0)  * LDA + kk], LDA);
                wmma::load_matrix_sync(a1, &A_s[(wm * 32 + 16) * LDA + kk], LDA);
                wmma::load_matrix_sync(b0, &B_s[(wn * 32 + 0)  * LDB + kk], LDB);
                wmma::load_matrix_sync(b1, &B_s[(wn * 32 + 16) * LDB + kk], LDB);
                wmma::mma_sync(c[0][0], a0, b0, c[0][0]);
                wmma::mma_sync(c[0][1], a0, b1, c[0][1]);
                wmma::mma_sync(c[1][0], a1, b0, c[1][0]);
                wmma::mma_sync(c[1][1], a1, b1, c[1][1]);
            }
        }
        __syncthreads();   // all warps done reading A_s/B_s before aliasing as C_s

        #pragma unroll
        for (int i = 0; i < 2; i++)
            #pragma unroll
            for (int j = 0; j < 2; j++)
                wmma::store_matrix_sync(&C_s[(wm * 32 + i * 16) * LDC + wn * 32 + j * 16],
                                        c[i][j], LDC, wmma::mem_row_major);
        __syncthreads();

        // epilogue: softplus + row reduction. 4 threads per row.
        {
            int row  = tid >> 2;
            int quad = tid & 3;
            const float* crow = &C_s[row * LDC + quad * 32];
            const float* coff = &g_c[n0 + quad * 32];
            float s = 0.0f;
            #pragma unroll
            for (int j = 0; j < 32; j++) {
                float l = crow[j] + coff[j];
                // sigmoid_xent(l, 0) = max(l,0) + log1p(exp(-|l|))
                s += fmaxf(l, 0.0f) + __logf(1.0f + __expf(-fabsf(l)));
            }
            s += __shfl_down_sync(0xffffffffu, s, 2);
            s += __shfl_down_sync(0xffffffffu, s, 1);
            if (quad == 0) rowAcc[row] += s;
        }
        // next iteration's leading __syncthreads protects C_s reuse
    }
    __syncthreads();
    if (tid < BM) g_partial[m0 + tid] = rowAcc[tid];
}

// ---------------- true logits: one warp per batch row ----------------
__global__ void k_true(const float* __restrict__ emb, const int* __restrict__ tgt,
                       const float* __restrict__ W, const float* __restrict__ bias) {
    int row  = blockIdx.x * 8 + (threadIdx.x >> 5);
    int lane = threadIdx.x & 31;
    if (row >= BATCH) return;
    int id = tgt[row];
    const float4* e4 = (const float4*)(emb + (size_t)row * EMBED);
    const float4* w4 = (const float4*)(W + (size_t)id * EMBED);
    float s = 0.0f;
    #pragma unroll
    for (int i = 0; i < 2; i++) {
        float4 a = e4[lane + i * 32];
        float4 b = w4[lane + i * 32];
        s += a.x * b.x + a.y * b.y + a.z * b.z + a.w * b.w;
    }
    #pragma unroll
    for (int off = 16; off > 0; off >>= 1)
        s += __shfl_down_sync(0xffffffffu, s, off);
    if (lane == 0) {
        float tl = s + bias[id] + neg_log_ec((float)id);
        // sigmoid_xent(tl, 1) = max(tl,0) - tl + log1p(exp(-|tl|))
        float loss = fmaxf(tl, 0.0f) - tl + log1pf(expf(-fabsf(tl)));
        g_partial[row] += loss;
    }
}

// ---------------- final mean ----------------
__global__ void k_final(float* __restrict__ out) {
    __shared__ double red[256];
    double s = 0.0;
    for (int i = threadIdx.x; i < BATCH; i += 256) s += (double)g_partial[i];
    red[threadIdx.x] = s;
    __syncthreads();
    for (int st = 128; st > 0; st >>= 1) {
        if (threadIdx.x < st) red[threadIdx.x] += red[threadIdx.x + st];
        __syncthreads();
    }
    if (threadIdx.x == 0) out[0] = (float)(red[0] / (double)BATCH);
}

// ---------------- launch ----------------
extern "C" void kernel_launch(void* const* d_in, const int* in_sizes, int n_in,
                              void* d_out, int out_size) {
    const float* emb  = (const float*)d_in[0];
    const int*   tgt  = (const int*)d_in[1];
    const int*   sids = (const int*)d_in[2];
    const float* W    = (const float*)d_in[3];
    const float* bias = (const float*)d_in[4];
    float*       out  = (float*)d_out;

    k_prep_A<<<(BATCH * 32) / 256, 256>>>(emb);
    k_prep_B<<<(NS * 32) / 256, 256>>>(sids, W);
    k_prep_c<<<NS / 256, 256>>>(sids, bias);
    k_gemm<<<BATCH / BM, 256>>>();
    k_true<<<BATCH / 8, 256>>>(emb, tgt, W, bias);
    k_final<<<1, 256>>>(out);
}

// round 2
// speedup vs baseline: 2.0796x; 2.0796x over previous
#include <cuda_runtime.h>
#include <cuda_bf16.h>

#define BATCH 16384
#define EMBED 256
#define NS    4096
#define VOCAB 50000

#define LDA 264   // A_s row stride (elems): 528B -> 4-bank shift/row, conflict-free ldmatrix
#define LDB 72    // B_s row stride (elems): 144B -> 4-bank shift/row, conflict-free ldmatrix
#define SMEM_A_BYTES (128 * LDA * 2)        // 67584
#define SMEM_B_BYTES (2 * 128 * LDB * 2)    // 36864 (double buffered)
#define SMEM_RED_BYTES (2 * 128 * 4)        // 1024
#define SMEM_TOTAL (SMEM_A_BYTES + SMEM_B_BYTES + SMEM_RED_BYTES)

// ---------------- device scratch ----------------
__device__ __align__(16) __nv_bfloat16 g_Bw[NS * EMBED]; // gathered sampled weights, bf16
__device__ float g_c[NS];                                // bias[id] - log(expected_count)
__device__ float g_ps[2][BATCH];                         // per-row partial losses (2 N-halves)

__device__ __forceinline__ float neg_log_ec(float fid) {
    const float inv_logv = 1.0f / logf((float)VOCAB + 1.0f);
    float p  = (logf(fid + 2.0f) - logf(fid + 1.0f)) * inv_logv;
    float ec = -expm1f((float)NS * log1pf(-p));
    return -logf(ec);
}

__device__ __forceinline__ unsigned su32(const void* p) {
    return (unsigned)__cvta_generic_to_shared(p);
}

// ---------------- prep: gather sampled weight rows -> bf16 ----------------
__global__ void k_prep_B(const int* __restrict__ sids, const float* __restrict__ W) {
    int i = blockIdx.x * 256 + threadIdx.x;
    if (i >= NS * 32) return;
    int s  = i >> 5;
    int d8 = (i & 31) << 3;
    int id = sids[s];
    const float4* src = (const float4*)(W + (size_t)id * EMBED + d8);
    float4 x = src[0], y = src[1];
    __align__(16) __nv_bfloat162 p[4];
    p[0] = __floats2bfloat162_rn(x.x, x.y);
    p[1] = __floats2bfloat162_rn(x.z, x.w);
    p[2] = __floats2bfloat162_rn(y.x, y.y);
    p[3] = __floats2bfloat162_rn(y.z, y.w);
    *(uint4*)(g_Bw + (size_t)s * EMBED + d8) = *(const uint4*)p;
}

__global__ void k_prep_c(const int* __restrict__ sids, const float* __restrict__ bias) {
    int s = blockIdx.x * 256 + threadIdx.x;
    if (s >= NS) return;
    int id = sids[s];
    g_c[s] = bias[id] + neg_log_ec((float)id);
}

// ---------------- fused GEMM + softplus row-sum (mma PTX, register epilogue) --
// Block: 256 thr (8 warps: 4 in M x 2 in N). Block tile: 128(M) x 128(N) per nt.
// A (128x256) resident in smem; B streamed in 128x64 chunks, cp.async double-buf.
__global__ __launch_bounds__(256, 2) void k_gemm(const float* __restrict__ emb) {
    extern __shared__ __align__(16) unsigned char sm[];
    __nv_bfloat16* A_s = (__nv_bfloat16*)sm;
    __nv_bfloat16* B_s = (__nv_bfloat16*)(sm + SMEM_A_BYTES);
    float*         red = (float*)(sm + SMEM_A_BYTES + SMEM_B_BYTES);

    const int tid  = threadIdx.x;
    const int lane = tid & 31;
    const int warp = tid >> 5;
    const int wm   = warp & 3;   // M group of 32
    const int wn   = warp >> 2;  // N group of 64
    const int mb   = blockIdx.x >> 1;
    const int half = blockIdx.x & 1;
    const int m0   = mb * 128;
    const int nb0  = half * (NS / 2);

    // ---- load + convert resident A (128 x 256 fp32 -> bf16) ----
    #pragma unroll 4
    for (int i = 0; i < 32; i++) {
        int idx = tid + i * 256;
        int r = idx >> 6;
        int c = (idx & 63) * 4;
        float4 v = *(const float4*)(emb + (size_t)(m0 + r) * EMBED + c);
        __align__(8) __nv_bfloat162 p[2];
        p[0] = __floats2bfloat162_rn(v.x, v.y);
        p[1] = __floats2bfloat162_rn(v.z, v.w);
        *(uint2*)(A_s + r * LDA + c) = *(const uint2*)p;
    }

    // ---- B chunk loader: chunk ch = (nt, kb), 128 rows x 64 K, 16KB ----
    auto load_chunk = [&](int buf, int ch) {
        int nt = ch >> 2, kb = ch & 3;
        const __nv_bfloat16* sb = g_Bw + (size_t)(nb0 + nt * 128) * EMBED + kb * 64;
        #pragma unroll
        for (int i = 0; i < 4; i++) {
            int c = tid + i * 256;
            int n = c >> 3, k8 = (c & 7) * 8;
            unsigned dst = su32(B_s + buf * 128 * LDB + n * LDB + k8);
            const void* src = sb + (size_t)n * EMBED + k8;
            asm volatile("cp.async.cg.shared.global [%0], [%1], 16;\n"
                         :: "r"(dst), "l"(src));
        }
    };

    float acc[2][8][4];
    #pragma unroll
    for (int mi = 0; mi < 2; mi++)
        #pragma unroll
        for (int ni = 0; ni < 8; ni++)
            #pragma unroll
            for (int q = 0; q < 4; q++) acc[mi][ni][q] = 0.0f;
    float rs[4] = {0.f, 0.f, 0.f, 0.f};

    load_chunk(0, 0);
    asm volatile("cp.async.commit_group;\n");
    __syncthreads();   // A_s ready for all

    int buf = 0;
    const int NCH = (NS / 2 / 128) * 4;   // 64 chunks
    for (int ch = 0; ch < NCH; ch++) {
        if (ch + 1 < NCH) {
            load_chunk(buf ^ 1, ch + 1);
            asm volatile("cp.async.commit_group;\n");
            asm volatile("cp.async.wait_group 1;\n");
        } else {
            asm volatile("cp.async.wait_group 0;\n");
        }
        __syncthreads();   // chunk ch visible in B_s[buf]

        const int kb = ch & 3;
        #pragma unroll
        for (int kk = 0; kk < 64; kk += 16) {
            const int kg = kb * 64 + kk;
            unsigned a[2][4];
            #pragma unroll
            for (int mi = 0; mi < 2; mi++) {
                unsigned addr = su32(A_s + (wm * 32 + mi * 16 + (lane & 15)) * LDA
                                         + kg + ((lane >> 4) << 3));
                asm volatile("ldmatrix.sync.aligned.m8n8.x4.shared.b16 {%0,%1,%2,%3}, [%4];\n"
                    : "=r"(a[mi][0]), "=r"(a[mi][1]), "=r"(a[mi][2]), "=r"(a[mi][3])
                    : "r"(addr));
            }
            unsigned b[8][2];
            #pragma unroll
            for (int np = 0; np < 4; np++) {
                unsigned addr = su32(B_s + buf * 128 * LDB
                                     + (wn * 64 + np * 16 + ((lane >> 4) << 3) + (lane & 7)) * LDB
                                     + kk + ((lane >> 3) & 1) * 8);
                asm volatile("ldmatrix.sync.aligned.m8n8.x4.shared.b16 {%0,%1,%2,%3}, [%4];\n"
                    : "=r"(b[np * 2][0]), "=r"(b[np * 2][1]),
                      "=r"(b[np * 2 + 1][0]), "=r"(b[np * 2 + 1][1])
                    : "r"(addr));
            }
            #pragma unroll
            for (int mi = 0; mi < 2; mi++)
                #pragma unroll
                for (int ni = 0; ni < 8; ni++)
                    asm volatile(
                        "mma.sync.aligned.m16n8k16.row.col.f32.bf16.bf16.f32 "
                        "{%0,%1,%2,%3},{%4,%5,%6,%7},{%8,%9},{%0,%1,%2,%3};\n"
                        : "+f"(acc[mi][ni][0]), "+f"(acc[mi][ni][1]),
                          "+f"(acc[mi][ni][2]), "+f"(acc[mi][ni][3])
                        : "r"(a[mi][0]), "r"(a[mi][1]), "r"(a[mi][2]), "r"(a[mi][3]),
                          "r"(b[ni][0]), "r"(b[ni][1]));
        }

        if (kb == 3) {
            // ---- register epilogue for tile nt ----
            const int nt = ch >> 2;
            const float* cp = g_c + nb0 + nt * 128 + wn * 64 + (lane & 3) * 2;
            #pragma unroll
            for (int mi = 0; mi < 2; mi++) {
                float lin0 = 0.f, lin1 = 0.f, pr0 = 1.f, pr1 = 1.f;
                #pragma unroll
                for (int ni = 0; ni < 8; ni++) {
                    float2 cf = *(const float2*)(cp + ni * 8);
                    float l0 = acc[mi][ni][0] + cf.x;
                    float l1 = acc[mi][ni][1] + cf.y;
                    float l2 = acc[mi][ni][2] + cf.x;
                    float l3 = acc[mi][ni][3] + cf.y;
                    lin0 += fmaxf(l0, 0.f) + fmaxf(l1, 0.f);
                    lin1 += fmaxf(l2, 0.f) + fmaxf(l3, 0.f);
                    pr0 *= (1.f + __expf(-fabsf(l0))) * (1.f + __expf(-fabsf(l1)));
                    pr1 *= (1.f + __expf(-fabsf(l2))) * (1.f + __expf(-fabsf(l3)));
                    acc[mi][ni][0] = 0.f; acc[mi][ni][1] = 0.f;
                    acc[mi][ni][2] = 0.f; acc[mi][ni][3] = 0.f;
                }
                rs[mi * 2 + 0] += lin0 + __logf(pr0);   // rows: mi*16 + lane/4
                rs[mi * 2 + 1] += lin1 + __logf(pr1);   // rows: mi*16 + 8 + lane/4
            }
        }
        __syncthreads();   // all reads of B_s[buf] done before it is refilled
        buf ^= 1;
    }

    // ---- reduce row sums: quad lanes hold same rows, disjoint columns ----
    #pragma unroll
    for (int s = 0; s < 4; s++) {
        rs[s] += __shfl_xor_sync(0xffffffffu, rs[s], 1);
        rs[s] += __shfl_xor_sync(0xffffffffu, rs[s], 2);
    }
    if ((lane & 3) == 0) {
        #pragma unroll
        for (int s = 0; s < 4; s++) {
            int mi = s >> 1, hi = s & 1;
            int row = wm * 32 + mi * 16 + hi * 8 + (lane >> 2);
            red[wn * 128 + row] = rs[s];
        }
    }
    __syncthreads();
    if (tid < 128)
        g_ps[half][m0 + tid] = red[tid] + red[128 + tid];
}

// ---------------- true logits: one warp per batch row ----------------
__global__ void k_true(const float* __restrict__ emb, const int* __restrict__ tgt,
                       const float* __restrict__ W, const float* __restrict__ bias) {
    int row  = blockIdx.x * 8 + (threadIdx.x >> 5);
    int lane = threadIdx.x & 31;
    if (row >= BATCH) return;
    int id = tgt[row];
    const float4* e4 = (const float4*)(emb + (size_t)row * EMBED);
    const float4* w4 = (const float4*)(W + (size_t)id * EMBED);
    float s = 0.0f;
    #pragma unroll
    for (int i = 0; i < 2; i++) {
        float4 a = e4[lane + i * 32];
        float4 b = w4[lane + i * 32];
        s += a.x * b.x + a.y * b.y + a.z * b.z + a.w * b.w;
    }
    #pragma unroll
    for (int off = 16; off > 0; off >>= 1)
        s += __shfl_down_sync(0xffffffffu, s, off);
    if (lane == 0) {
        float tl = s + bias[id] + neg_log_ec((float)id);
        float loss = fmaxf(tl, 0.0f) - tl + log1pf(expf(-fabsf(tl)));
        g_ps[0][row] += loss;
    }
}

// ---------------- final mean ----------------
__global__ void k_final(float* __restrict__ out) {
    __shared__ double redd[256];
    double s = 0.0;
    for (int i = threadIdx.x; i < BATCH; i += 256)
        s += (double)g_ps[0][i] + (double)g_ps[1][i];
    redd[threadIdx.x] = s;
    __syncthreads();
    for (int st = 128; st > 0; st >>= 1) {
        if (threadIdx.x < st) redd[threadIdx.x] += redd[threadIdx.x + st];
        __syncthreads();
    }
    if (threadIdx.x == 0) out[0] = (float)(redd[0] / (double)BATCH);
}

// ---------------- launch ----------------
extern "C" void kernel_launch(void* const* d_in, const int* in_sizes, int n_in,
                              void* d_out, int out_size) {
    const float* emb  = (const float*)d_in[0];
    const int*   tgt  = (const int*)d_in[1];
    const int*   sids = (const int*)d_in[2];
    const float* W    = (const float*)d_in[3];
    const float* bias = (const float*)d_in[4];
    float*       out  = (float*)d_out;

    cudaFuncSetAttribute(k_gemm, cudaFuncAttributeMaxDynamicSharedMemorySize, SMEM_TOTAL);

    k_prep_B<<<(NS * 32) / 256, 256>>>(sids, W);
    k_prep_c<<<NS / 256, 256>>>(sids, bias);
    k_gemm<<<256, 256, SMEM_TOTAL>>>(emb);
    k_true<<<BATCH / 8, 256>>>(emb, tgt, W, bias);
    k_final<<<1, 256>>>(out);
}